// round 14
// baseline (speedup 1.0000x reference)
#include <cuda_runtime.h>
#include <cuda_fp16.h>
#include <math.h>
#include <stdint.h>

// Problem shape (fixed by dataset)
#define L   4096
#define D   1024
#define SN  16
#define NC  64      // number of chunks
#define CT  64      // chunk length; NC*CT == L

typedef unsigned long long u64;

// ---------------- scratch (static device globals; no allocation) ----------------
__device__ float g_xn[L * D];                  // normalized input (fp32)
__device__ __half g_xh[L * D];                 // fp16 hi of xn
__device__ __half g_xl[L * D];                 // fp16 lo of xn (bc tile only)
__device__ __half g_wth[D * D];                // W_delta^T fp16 [n][k]
__device__ __half g_wbch[128 * D];             // [WB|WC|0]^T hi [n][k], n<32 real
__device__ __half g_wbcl[128 * D];             // [WB|WC|0]^T lo
__device__ float g_delta[L * D];               // selective delta
__device__ float g_sdx[L * D];                 // sqrt(delta) * xn
__device__ float g_bpc[L * 2 * SN];            // per-t: Bp[0..15], C[16..31]
__device__ float g_cA[D * SN];                 // +0.5*exp(A_log)   (positive!)
__device__ float g_P[NC * D * SN];             // per-chunk product of A_bar
__device__ float g_S[NC * D * SN];             // per-chunk end-state from h0=0
__device__ float g_hin[NC * D * SN];           // per-chunk initial state

// ---------------- helpers ----------------
__device__ __forceinline__ float frcp(float x) {
    float r;
    asm("rcp.approx.f32 %0, %1;" : "=f"(r) : "f"(x));
    return r;
}
__device__ __forceinline__ uint32_t smem_u32(const void* p) {
    uint32_t a;
    asm("{ .reg .u64 t; cvta.to.shared.u64 t, %1; cvt.u32.u64 %0, t; }" : "=r"(a) : "l"(p));
    return a;
}
__device__ __forceinline__ void ldsm4(uint32_t& r0, uint32_t& r1, uint32_t& r2, uint32_t& r3,
                                      uint32_t addr) {
    asm volatile("ldmatrix.sync.aligned.m8n8.x4.shared.b16 {%0,%1,%2,%3}, [%4];"
                 : "=r"(r0), "=r"(r1), "=r"(r2), "=r"(r3) : "r"(addr));
}
__device__ __forceinline__ void mma16816(float* d, const uint32_t* a, uint32_t b0, uint32_t b1) {
    asm volatile(
        "mma.sync.aligned.m16n8k16.row.col.f32.f16.f16.f32 "
        "{%0,%1,%2,%3}, {%4,%5,%6,%7}, {%8,%9}, {%0,%1,%2,%3};"
        : "+f"(d[0]), "+f"(d[1]), "+f"(d[2]), "+f"(d[3])
        : "r"(a[0]), "r"(a[1]), "r"(a[2]), "r"(a[3]), "r"(b0), "r"(b1));
}
__device__ __forceinline__ void cp16(uint32_t dst, const void* src) {
    asm volatile("cp.async.cg.shared.global [%0], [%1], 16;" :: "r"(dst), "l"(src) : "memory");
}
__device__ __forceinline__ u64 pack2(float lo, float hi) {
    u64 r;
    asm("mov.b64 %0, {%1,%2};" : "=l"(r) : "f"(lo), "f"(hi));
    return r;
}
__device__ __forceinline__ float2 unpack2(u64 v) {
    float lo, hi;
    asm("mov.b64 {%0,%1}, %2;" : "=f"(lo), "=f"(hi) : "l"(v));
    return make_float2(lo, hi);
}
__device__ __forceinline__ u64 fma2(u64 a, u64 b, u64 c) {
    u64 d;
    asm("fma.rn.f32x2 %0, %1, %2, %3;" : "=l"(d) : "l"(a), "l"(b), "l"(c));
    return d;
}
__device__ __forceinline__ u64 mul2(u64 a, u64 b) {
    u64 d;
    asm("mul.rn.f32x2 %0, %1, %2;" : "=l"(d) : "l"(a), "l"(b));
    return d;
}
__device__ __forceinline__ u64 add2(u64 a, u64 b) {
    u64 d;
    asm("add.rn.f32x2 %0, %1, %2;" : "=l"(d) : "l"(a), "l"(b));
    return d;
}

// ---------------- kernel 0b: transpose W_delta -> fp16 ----------------
__global__ __launch_bounds__(256) void k_wt(const float* __restrict__ W) {
    __shared__ float tile[32][33];
    int bx = blockIdx.x, by = blockIdx.y;
    int tx = threadIdx.x, ty = threadIdx.y;   // 32 x 8
    #pragma unroll
    for (int i = 0; i < 32; i += 8)
        tile[ty + i][tx] = W[(size_t)(by * 32 + ty + i) * D + bx * 32 + tx];
    __syncthreads();
    #pragma unroll
    for (int i = 0; i < 32; i += 8) {
        int n = bx * 32 + ty + i;
        int k = by * 32 + tx;
        g_wth[(size_t)n * D + k] = __float2half(tile[tx][ty + i]);  // = W[k][n]
    }
}

// ---------------- kernel 0c: pack [WB|WC|0]^T fp16 hi/lo, + cA ----------------
__global__ __launch_bounds__(256) void k_wbc(const float* __restrict__ WB,
                                             const float* __restrict__ WC,
                                             const float* __restrict__ A_log) {
    int idx = blockIdx.x * 256 + threadIdx.x;   // 128*1024
    if (idx < D * SN) g_cA[idx] = 0.5f * expf(A_log[idx]);
    int n = idx >> 10, k = idx & 1023;
    float v = 0.f;
    if (n < SN) v = WB[(size_t)k * SN + n];
    else if (n < 2 * SN) v = WC[(size_t)k * SN + n - SN];
    __half h = __float2half(v);
    __half l = __float2half(v - __half2float(h));
    g_wbch[idx] = h;
    g_wbcl[idx] = l;
}

// ---------------- kernel 1: RMSNorm (+ fp16 hi/lo split of xn) ----------------
__global__ __launch_bounds__(256) void k_rms(const float* __restrict__ x,
                                             const float* __restrict__ w) {
    int row = blockIdx.x;
    int tid = threadIdx.x;
    const float4 xv = *(const float4*)(x + (size_t)row * D + tid * 4);
    float s = xv.x * xv.x + xv.y * xv.y + xv.z * xv.z + xv.w * xv.w;
    #pragma unroll
    for (int o = 16; o > 0; o >>= 1) s += __shfl_xor_sync(0xFFFFFFFFu, s, o);
    __shared__ float red[8];
    int warp = tid >> 5, lane = tid & 31;
    if (lane == 0) red[warp] = s;
    __syncthreads();
    float tot = 0.f;
    #pragma unroll
    for (int i = 0; i < 8; i++) tot += red[i];
    float inv = 1.0f / sqrtf(tot * (1.0f / (float)D) + 1e-6f);
    const float4 wv = *(const float4*)(w + tid * 4);
    float4 o;
    o.x = wv.x * xv.x * inv;
    o.y = wv.y * xv.y * inv;
    o.z = wv.z * xv.z * inv;
    o.w = wv.w * xv.w * inv;
    size_t base = (size_t)row * D + tid * 4;
    *(float4*)(&g_xn[base]) = o;
    float vv[4] = {o.x, o.y, o.z, o.w};
    __half hh[4], ll[4];
    #pragma unroll
    for (int i = 0; i < 4; i++) {
        hh[i] = __float2half(vv[i]);
        ll[i] = __float2half(vv[i] - __half2float(hh[i]));
    }
    ((__half2*)(&g_xh[base]))[0] = __halves2half2(hh[0], hh[1]);
    ((__half2*)(&g_xh[base]))[1] = __halves2half2(hh[2], hh[3]);
    ((__half2*)(&g_xl[base]))[0] = __halves2half2(ll[0], ll[1]);
    ((__half2*)(&g_xl[base]))[1] = __halves2half2(ll[2], ll[3]);
}

// ---------------- kernel 3: fused GEMM (delta + Bp/C) via mma.sync fp16 ----------------
// grid (9, 32): bn<8 -> delta path: BK=64, XOR-swizzled 128B rows, 16 iters.
//               bn==8 -> bc path: BK=32, KST=40 layout, 32 iters.
// CTA tile 128x128, 8 warps each 32(m) x 64(n). cp.async 2-stage pipeline.
#define KST 40                         // bc path smem row stride in fp16 (80B)
#define TILE_B (128 * KST * 2)         // 10240 B per bc tile
#define STAGE_B (4 * TILE_B)           // 40960 B per bc stage
#define TILE2  16384                   // delta tile: 128 rows x 128B
#define STAGE2 (2 * TILE2)             // 32768 B per delta stage
#define SMEM_TOT (2 * STAGE_B)         // 81920 B (covers both layouts)
__global__ __launch_bounds__(256, 2) void k_gemm_mma(const float* __restrict__ bd) {
    extern __shared__ __align__(16) char smem[];
    const uint32_t su = smem_u32(smem);

    int tid = threadIdx.x, wid = tid >> 5, lane = tid & 31;
    int bm = blockIdx.y, bn = blockIdx.x;
    const int m0 = bm * 128, n0 = bn * 128;
    int wm = wid & 3, wn = wid >> 2;

    float acc[2][8][4];
    #pragma unroll
    for (int a = 0; a < 2; a++)
        #pragma unroll
        for (int b = 0; b < 8; b++)
            #pragma unroll
            for (int c = 0; c < 4; c++) acc[a][b][c] = 0.f;

    if (bn < 8) {
        // ================= delta path: BK=64, swizzled =================
        const __half* pA = g_xh + (size_t)m0 * D;
        const __half* pB = g_wth + (size_t)n0 * D;
        auto issue = [&](int k0, int stage) {
            uint32_t sb = su + (uint32_t)(stage * STAGE2);
            #pragma unroll
            for (int j = 0; j < 8; j++) {
                int id = tid + j * 256;
                const int tile = j >> 2;               // 0..1 (compile-time per j)
                int sub = id & 1023;
                int row = sub >> 3, kc = sub & 7;
                const __half* src = (tile == 0 ? pA : pB) + (size_t)row * D + k0 + kc * 8;
                uint32_t dst = sb + (uint32_t)(tile * TILE2 + row * 128 +
                                               ((kc ^ (row & 7)) << 4));
                cp16(dst, src);
            }
            asm volatile("cp.async.commit_group;" ::: "memory");
        };

        int arow = wm * 32 + (lane & 15);
        int brow = wn * 64 + (lane & 7) + ((lane >> 4) << 3);
        uint32_t abase = (uint32_t)(arow * 128);
        uint32_t bbase = (uint32_t)(TILE2 + brow * 128);
        uint32_t rl = (uint32_t)(lane & 7);
        uint32_t ahalf = (uint32_t)(lane >> 4);
        uint32_t bhalf = (uint32_t)((lane >> 3) & 1);

        issue(0, 0);
        for (int i = 0; i < 16; i++) {
            if (i > 0) __syncthreads();
            if (i + 1 < 16) issue((i + 1) * 64, (i + 1) & 1);
            if (i == 15) asm volatile("cp.async.wait_group 0;" ::: "memory");
            else         asm volatile("cp.async.wait_group 1;" ::: "memory");
            __syncthreads();

            uint32_t sb = su + (uint32_t)((i & 1) * STAGE2);
            #pragma unroll
            for (int kk = 0; kk < 4; kk++) {
                uint32_t xa = (((uint32_t)(2 * kk) + ahalf) ^ rl) << 4;
                uint32_t xb = (((uint32_t)(2 * kk) + bhalf) ^ rl) << 4;
                uint32_t ah0[4], ah1[4];
                ldsm4(ah0[0], ah0[1], ah0[2], ah0[3], sb + abase + xa);
                ldsm4(ah1[0], ah1[1], ah1[2], ah1[3], sb + abase + 2048 + xa);
                #pragma unroll
                for (int nb = 0; nb < 4; nb++) {
                    uint32_t bh[4];
                    ldsm4(bh[0], bh[1], bh[2], bh[3],
                          sb + bbase + (uint32_t)(nb * 2048) + xb);
                    mma16816(acc[0][2 * nb],     ah0, bh[0], bh[1]);
                    mma16816(acc[1][2 * nb],     ah1, bh[0], bh[1]);
                    mma16816(acc[0][2 * nb + 1], ah0, bh[2], bh[3]);
                    mma16816(acc[1][2 * nb + 1], ah1, bh[2], bh[3]);
                }
            }
        }

        // epilogue: z -> delta -> (delta, sqrt(delta)*xn)
        const float CTR = 5.00005f, HLF = 4.99995f, INVH = 1.0f / 4.99995f;
        #pragma unroll
        for (int ma = 0; ma < 2; ma++) {
            int row0 = m0 + wm * 32 + ma * 16 + (lane >> 2);
            #pragma unroll
            for (int na = 0; na < 8; na++) {
                int col = n0 + wn * 64 + na * 8 + 2 * (lane & 3);
                float2 bdv = *(const float2*)(bd + col);
                #pragma unroll
                for (int hrow = 0; hrow < 2; hrow++) {
                    int m = row0 + hrow * 8;
                    float z0 = acc[ma][na][2 * hrow]     + bdv.x;
                    float z1 = acc[ma][na][2 * hrow + 1] + bdv.y;
                    float2 xv = *(const float2*)(&g_xn[(size_t)m * D + col]);
                    float sp0 = fmaxf(z0, 0.0f) + log1pf(expf(-fabsf(z0)));
                    float sp1 = fmaxf(z1, 0.0f) + log1pf(expf(-fabsf(z1)));
                    float dl0 = CTR + HLF * tanhf((sp0 - CTR) * INVH);
                    float dl1 = CTR + HLF * tanhf((sp1 - CTR) * INVH);
                    float sx0 = sqrtf(dl0) * xv.x;
                    float sx1 = sqrtf(dl1) * xv.y;
                    *(float2*)(&g_delta[(size_t)m * D + col]) = make_float2(dl0, dl1);
                    *(float2*)(&g_sdx[(size_t)m * D + col])   = make_float2(sx0, sx1);
                }
            }
        }
    } else {
        // ================= bc path: BK=32, KST=40 =================
        const __half* pA0 = g_xh + (size_t)m0 * D;
        const __half* pA1 = g_xl + (size_t)m0 * D;
        const __half* pB0 = g_wbch;
        const __half* pB1 = g_wbcl;

        uint32_t aoff = (uint32_t)((wm * 32 + (lane & 15)) * (KST * 2) + ((lane >> 4) << 4));
        uint32_t boff = (uint32_t)((wn * 64 + (lane & 7) + ((lane >> 4) << 3)) * (KST * 2) +
                                   (((lane >> 3) & 1) << 4));

        auto issue = [&](int k0, int stage) {
            uint32_t sb = su + (uint32_t)(stage * STAGE_B);
            #pragma unroll
            for (int j = 0; j < 8; j++) {
                const int tile = j >> 1;
                int sub = tid + (j & 1) * 256;
                int row = sub >> 2, seg = sub & 3;
                const __half* src;
                if (tile == 0)      src = pA0 + (size_t)row * D + k0 + seg * 8;
                else if (tile == 1) src = pA1 + (size_t)row * D + k0 + seg * 8;
                else if (tile == 2) src = pB0 + (size_t)row * D + k0 + seg * 8;
                else                src = pB1 + (size_t)row * D + k0 + seg * 8;
                cp16(sb + (uint32_t)(tile * TILE_B + row * (KST * 2) + seg * 16), src);
            }
            asm volatile("cp.async.commit_group;" ::: "memory");
        };

        issue(0, 0);
        for (int i = 0; i < 32; i++) {
            if (i > 0) __syncthreads();
            if (i + 1 < 32) issue((i + 1) * 32, (i + 1) & 1);
            if (i == 31) asm volatile("cp.async.wait_group 0;" ::: "memory");
            else         asm volatile("cp.async.wait_group 1;" ::: "memory");
            __syncthreads();

            uint32_t sb = su + (uint32_t)((i & 1) * STAGE_B);
            uint32_t uAh = sb, uAl = sb + TILE_B, uBh = sb + 2 * TILE_B, uBl = sb + 3 * TILE_B;
            #pragma unroll
            for (int kk = 0; kk < 2; kk++) {
                uint32_t kb = (uint32_t)(kk * 32);
                uint32_t ah0[4], ah1[4];
                ldsm4(ah0[0], ah0[1], ah0[2], ah0[3], uAh + aoff + kb);
                ldsm4(ah1[0], ah1[1], ah1[2], ah1[3], uAh + aoff + kb + 16 * KST * 2);
                #pragma unroll
                for (int nb = 0; nb < 2; nb++) {      // bc: only cols 0..31
                    if (wn == 1) continue;
                    uint32_t bh[4];
                    uint32_t bo = boff + kb + (uint32_t)(nb * 16 * KST * 2);
                    ldsm4(bh[0], bh[1], bh[2], bh[3], uBh + bo);
                    mma16816(acc[0][2 * nb],     ah0, bh[0], bh[1]);
                    mma16816(acc[1][2 * nb],     ah1, bh[0], bh[1]);
                    mma16816(acc[0][2 * nb + 1], ah0, bh[2], bh[3]);
                    mma16816(acc[1][2 * nb + 1], ah1, bh[2], bh[3]);
                    uint32_t al0[4], al1[4], bl[4];
                    ldsm4(al0[0], al0[1], al0[2], al0[3], uAl + aoff + kb);
                    ldsm4(al1[0], al1[1], al1[2], al1[3], uAl + aoff + kb + 16 * KST * 2);
                    ldsm4(bl[0], bl[1], bl[2], bl[3], uBl + bo);
                    mma16816(acc[0][2 * nb],     al0, bh[0], bh[1]);
                    mma16816(acc[1][2 * nb],     al1, bh[0], bh[1]);
                    mma16816(acc[0][2 * nb + 1], al0, bh[2], bh[3]);
                    mma16816(acc[1][2 * nb + 1], al1, bh[2], bh[3]);
                    mma16816(acc[0][2 * nb],     ah0, bl[0], bl[1]);
                    mma16816(acc[1][2 * nb],     ah1, bl[0], bl[1]);
                    mma16816(acc[0][2 * nb + 1], ah0, bl[2], bl[3]);
                    mma16816(acc[1][2 * nb + 1], ah1, bl[2], bl[3]);
                }
            }
        }

        if (wn == 0) {
            #pragma unroll
            for (int ma = 0; ma < 2; ma++) {
                int row0 = m0 + wm * 32 + ma * 16 + (lane >> 2);
                #pragma unroll
                for (int na = 0; na < 4; na++) {
                    int col = na * 8 + 2 * (lane & 3);
                    #pragma unroll
                    for (int hrow = 0; hrow < 2; hrow++) {
                        int m = row0 + hrow * 8;
                        *(float2*)(&g_bpc[(size_t)m * 2 * SN + col]) =
                            make_float2(acc[ma][na][2 * hrow], acc[ma][na][2 * hrow + 1]);
                    }
                }
            }
        }
    }
}

// ---------------- kernel 4: chunk-local scan, n-split S=4 (4 states/thread) ----------------
// gid = c*4096 + d*4 + s; thread handles n in [s*4, s*4+4). 256K threads total.
__global__ __launch_bounds__(256) void k_phase2() {
    int gid = blockIdx.x * 256 + threadIdx.x;
    int c = gid >> 12;
    int j = gid & 4095;
    int d = j >> 2;
    int s = j & 3;
    const u64 ONE2 = pack2(1.f, 1.f), TWO2 = pack2(2.f, 2.f), NONE2 = pack2(-1.f, -1.f);
    u64 cA2[2], h2[2], P2[2];
    {
        ulonglong2 v = *(const ulonglong2*)&g_cA[d * SN + s * 4];
        cA2[0] = v.x; cA2[1] = v.y;
    }
    h2[0] = h2[1] = 0ull;
    P2[0] = P2[1] = ONE2;

    int t0 = c * CT;
    for (int tt = 0; tt < CT; tt++) {
        int t = t0 + tt;
        float dlv = g_delta[(size_t)t * D + d];
        float sdx = g_sdx[(size_t)t * D + d];
        ulonglong2 vb = *(const ulonglong2*)&g_bpc[(size_t)t * 2 * SN + s * 4];
        u64 dlv2 = pack2(dlv, dlv), sdx2 = pack2(sdx, sdx);
        u64 bp2[2] = {vb.x, vb.y};
        #pragma unroll
        for (int p = 0; p < 2; p++) {
            u64 den2 = fma2(cA2[p], dlv2, ONE2);       // 1 + 0.5*delta*|A| > 1
            float2 dd = unpack2(den2);
            u64 dinv2 = pack2(frcp(dd.x), frcp(dd.y));
            u64 ab2 = fma2(dinv2, TWO2, NONE2);        // (1+hf)/(1-hf) = 2*dinv - 1
            u64 bx2 = mul2(mul2(bp2[p], dinv2), sdx2);
            h2[p] = fma2(ab2, h2[p], bx2);
            P2[p] = mul2(P2[p], ab2);
        }
    }
    size_t basei = (size_t)c * (D * SN) + (size_t)d * SN + s * 4;
    ulonglong2 vp, vs;
    vp.x = P2[0]; vp.y = P2[1];
    vs.x = h2[0]; vs.y = h2[1];
    *(ulonglong2*)&g_P[basei] = vp;
    *(ulonglong2*)&g_S[basei] = vs;
}

// ---------------- kernel 5: scan over chunk summaries ----------------
__global__ __launch_bounds__(256) void k_phase3() {
    int s = blockIdx.x * 256 + threadIdx.x;  // D*SN threads
    float H = 0.f;
    #pragma unroll 4
    for (int c = 0; c < NC; c++) {
        size_t idx = (size_t)c * (D * SN) + s;
        g_hin[idx] = H;
        H = fmaf(g_P[idx], H, g_S[idx]);
    }
}

// ---------------- kernel 6: recompute with true init, emit y (n-split S=4) ----------------
__global__ __launch_bounds__(256) void k_phase4(const float* __restrict__ Dskip,
                                                float* __restrict__ y) {
    int gid = blockIdx.x * 256 + threadIdx.x;
    int c = gid >> 12;
    int j = gid & 4095;
    int d = j >> 2;
    int s = j & 3;
    const u64 ONE2 = pack2(1.f, 1.f), TWO2 = pack2(2.f, 2.f), NONE2 = pack2(-1.f, -1.f);
    u64 cA2[2], h2[2];
    {
        ulonglong2 v = *(const ulonglong2*)&g_cA[d * SN + s * 4];
        cA2[0] = v.x; cA2[1] = v.y;
    }
    size_t basei = (size_t)c * (D * SN) + (size_t)d * SN + s * 4;
    {
        ulonglong2 v = *(const ulonglong2*)&g_hin[basei];
        h2[0] = v.x; h2[1] = v.y;
    }
    float dsk = Dskip[d];

    int t0 = c * CT;
    for (int tt = 0; tt < CT; tt++) {
        int t = t0 + tt;
        float dlv = g_delta[(size_t)t * D + d];
        float sdx = g_sdx[(size_t)t * D + d];
        float xnv = g_xn[(size_t)t * D + d];
        ulonglong2 vb = *(const ulonglong2*)&g_bpc[(size_t)t * 2 * SN + s * 4];
        ulonglong2 vc = *(const ulonglong2*)&g_bpc[(size_t)t * 2 * SN + SN + s * 4];
        u64 dlv2 = pack2(dlv, dlv), sdx2 = pack2(sdx, sdx);
        u64 bp2[2] = {vb.x, vb.y};
        u64 cc2[2] = {vc.x, vc.y};
        u64 acca = 0ull, accb = 0ull;
        #pragma unroll
        for (int p = 0; p < 2; p++) {
            u64 den2 = fma2(cA2[p], dlv2, ONE2);
            float2 dd = unpack2(den2);
            u64 dinv2 = pack2(frcp(dd.x), frcp(dd.y));
            u64 ab2 = fma2(dinv2, TWO2, NONE2);
            u64 bx2 = mul2(mul2(bp2[p], dinv2), sdx2);
            h2[p] = fma2(ab2, h2[p], bx2);
            if (p) accb = fma2(cc2[p], h2[p], accb);
            else   acca = fma2(cc2[p], h2[p], acca);
        }
        float2 sv = unpack2(add2(acca, accb));
        float acc = sv.x + sv.y;
        // reduce across the 4-lane n-split group
        acc += __shfl_xor_sync(0xFFFFFFFFu, acc, 1);
        acc += __shfl_xor_sync(0xFFFFFFFFu, acc, 2);
        if (s == 0) y[(size_t)t * D + d] = fmaf(dsk, xnv, acc);
    }
}

// ---------------- launch ----------------
extern "C" void kernel_launch(void* const* d_in, const int* in_sizes, int n_in,
                              void* d_out, int out_size) {
    const float* x       = (const float*)d_in[0];
    const float* A_log   = (const float*)d_in[1];
    const float* W_delta = (const float*)d_in[2];
    const float* b_delta = (const float*)d_in[3];
    const float* W_B     = (const float*)d_in[4];
    const float* W_C     = (const float*)d_in[5];
    const float* D_skip  = (const float*)d_in[6];
    const float* norm_w  = (const float*)d_in[7];
    float* y = (float*)d_out;

    cudaFuncSetAttribute(k_gemm_mma, cudaFuncAttributeMaxDynamicSharedMemorySize,
                         SMEM_TOT);

    k_wt<<<dim3(32, 32), dim3(32, 8)>>>(W_delta);
    k_wbc<<<128 * D / 256, 256>>>(W_B, W_C, A_log);
    k_rms<<<L, 256>>>(x, norm_w);
    k_gemm_mma<<<dim3(9, 32), 256, SMEM_TOT>>>(b_delta);
    k_phase2<<<NC * D * 4 / 256, 256>>>();
    k_phase3<<<D * SN / 256, 256>>>();
    k_phase4<<<NC * D * 4 / 256, 256>>>(D_skip, y);
}

// round 15
// speedup vs baseline: 1.7722x; 1.7722x over previous
#include <cuda_runtime.h>
#include <cuda_fp16.h>
#include <math.h>
#include <stdint.h>

// Problem shape (fixed by dataset)
#define L   4096
#define D   1024
#define SN  16
#define NC  64      // number of chunks
#define CT  64      // chunk length; NC*CT == L
#define TB  16      // t-block for phase smem staging
#define NTB (CT / TB)

typedef unsigned long long u64;

// ---------------- scratch (static device globals; no allocation) ----------------
__device__ float g_xn[L * D];                  // normalized input (fp32)
__device__ __half g_xh[L * D];                 // fp16 hi of xn
__device__ __half g_xl[L * D];                 // fp16 lo of xn (bc tile only)
__device__ __half g_wth[D * D];                // W_delta^T fp16 [n][k]
__device__ __half g_wbch[128 * D];             // [WB|WC|0]^T hi [n][k], n<32 real
__device__ __half g_wbcl[128 * D];             // [WB|WC|0]^T lo
__device__ float g_delta[L * D];               // selective delta
__device__ float g_sdx[L * D];                 // sqrt(delta) * xn
__device__ float g_bpc[L * 2 * SN];            // per-t: Bp[0..15], C[16..31]
__device__ float g_cA[D * SN];                 // +0.5*exp(A_log)   (positive!)
__device__ float g_P[NC * D * SN];             // per-chunk product of A_bar
__device__ float g_S[NC * D * SN];             // per-chunk end-state from h0=0
__device__ float g_hin[NC * D * SN];           // per-chunk initial state

// ---------------- helpers ----------------
__device__ __forceinline__ float frcp(float x) {
    float r;
    asm("rcp.approx.f32 %0, %1;" : "=f"(r) : "f"(x));
    return r;
}
__device__ __forceinline__ uint32_t smem_u32(const void* p) {
    uint32_t a;
    asm("{ .reg .u64 t; cvta.to.shared.u64 t, %1; cvt.u32.u64 %0, t; }" : "=r"(a) : "l"(p));
    return a;
}
__device__ __forceinline__ void ldsm4(uint32_t& r0, uint32_t& r1, uint32_t& r2, uint32_t& r3,
                                      uint32_t addr) {
    asm volatile("ldmatrix.sync.aligned.m8n8.x4.shared.b16 {%0,%1,%2,%3}, [%4];"
                 : "=r"(r0), "=r"(r1), "=r"(r2), "=r"(r3) : "r"(addr));
}
__device__ __forceinline__ void mma16816(float* d, const uint32_t* a, uint32_t b0, uint32_t b1) {
    asm volatile(
        "mma.sync.aligned.m16n8k16.row.col.f32.f16.f16.f32 "
        "{%0,%1,%2,%3}, {%4,%5,%6,%7}, {%8,%9}, {%0,%1,%2,%3};"
        : "+f"(d[0]), "+f"(d[1]), "+f"(d[2]), "+f"(d[3])
        : "r"(a[0]), "r"(a[1]), "r"(a[2]), "r"(a[3]), "r"(b0), "r"(b1));
}
__device__ __forceinline__ void cp16(uint32_t dst, const void* src) {
    asm volatile("cp.async.cg.shared.global [%0], [%1], 16;" :: "r"(dst), "l"(src) : "memory");
}
__device__ __forceinline__ u64 pack2(float lo, float hi) {
    u64 r;
    asm("mov.b64 %0, {%1,%2};" : "=l"(r) : "f"(lo), "f"(hi));
    return r;
}
__device__ __forceinline__ float2 unpack2(u64 v) {
    float lo, hi;
    asm("mov.b64 {%0,%1}, %2;" : "=f"(lo), "=f"(hi) : "l"(v));
    return make_float2(lo, hi);
}
__device__ __forceinline__ u64 fma2(u64 a, u64 b, u64 c) {
    u64 d;
    asm("fma.rn.f32x2 %0, %1, %2, %3;" : "=l"(d) : "l"(a), "l"(b), "l"(c));
    return d;
}
__device__ __forceinline__ u64 mul2(u64 a, u64 b) {
    u64 d;
    asm("mul.rn.f32x2 %0, %1, %2;" : "=l"(d) : "l"(a), "l"(b));
    return d;
}
__device__ __forceinline__ u64 add2(u64 a, u64 b) {
    u64 d;
    asm("add.rn.f32x2 %0, %1, %2;" : "=l"(d) : "l"(a), "l"(b));
    return d;
}

// ---------------- kernel 0b: transpose W_delta -> fp16 ----------------
__global__ __launch_bounds__(256) void k_wt(const float* __restrict__ W) {
    __shared__ float tile[32][33];
    int bx = blockIdx.x, by = blockIdx.y;
    int tx = threadIdx.x, ty = threadIdx.y;   // 32 x 8
    #pragma unroll
    for (int i = 0; i < 32; i += 8)
        tile[ty + i][tx] = W[(size_t)(by * 32 + ty + i) * D + bx * 32 + tx];
    __syncthreads();
    #pragma unroll
    for (int i = 0; i < 32; i += 8) {
        int n = bx * 32 + ty + i;
        int k = by * 32 + tx;
        g_wth[(size_t)n * D + k] = __float2half(tile[tx][ty + i]);  // = W[k][n]
    }
}

// ---------------- kernel 0c: pack [WB|WC|0]^T fp16 hi/lo, + cA ----------------
__global__ __launch_bounds__(256) void k_wbc(const float* __restrict__ WB,
                                             const float* __restrict__ WC,
                                             const float* __restrict__ A_log) {
    int idx = blockIdx.x * 256 + threadIdx.x;   // 128*1024
    if (idx < D * SN) g_cA[idx] = 0.5f * expf(A_log[idx]);
    int n = idx >> 10, k = idx & 1023;
    float v = 0.f;
    if (n < SN) v = WB[(size_t)k * SN + n];
    else if (n < 2 * SN) v = WC[(size_t)k * SN + n - SN];
    __half h = __float2half(v);
    __half l = __float2half(v - __half2float(h));
    g_wbch[idx] = h;
    g_wbcl[idx] = l;
}

// ---------------- kernel 1: RMSNorm (+ fp16 hi/lo split of xn) ----------------
__global__ __launch_bounds__(256) void k_rms(const float* __restrict__ x,
                                             const float* __restrict__ w) {
    int row = blockIdx.x;
    int tid = threadIdx.x;
    const float4 xv = *(const float4*)(x + (size_t)row * D + tid * 4);
    float s = xv.x * xv.x + xv.y * xv.y + xv.z * xv.z + xv.w * xv.w;
    #pragma unroll
    for (int o = 16; o > 0; o >>= 1) s += __shfl_xor_sync(0xFFFFFFFFu, s, o);
    __shared__ float red[8];
    int warp = tid >> 5, lane = tid & 31;
    if (lane == 0) red[warp] = s;
    __syncthreads();
    float tot = 0.f;
    #pragma unroll
    for (int i = 0; i < 8; i++) tot += red[i];
    float inv = 1.0f / sqrtf(tot * (1.0f / (float)D) + 1e-6f);
    const float4 wv = *(const float4*)(w + tid * 4);
    float4 o;
    o.x = wv.x * xv.x * inv;
    o.y = wv.y * xv.y * inv;
    o.z = wv.z * xv.z * inv;
    o.w = wv.w * xv.w * inv;
    size_t base = (size_t)row * D + tid * 4;
    *(float4*)(&g_xn[base]) = o;
    float vv[4] = {o.x, o.y, o.z, o.w};
    __half hh[4], ll[4];
    #pragma unroll
    for (int i = 0; i < 4; i++) {
        hh[i] = __float2half(vv[i]);
        ll[i] = __float2half(vv[i] - __half2float(hh[i]));
    }
    ((__half2*)(&g_xh[base]))[0] = __halves2half2(hh[0], hh[1]);
    ((__half2*)(&g_xh[base]))[1] = __halves2half2(hh[2], hh[3]);
    ((__half2*)(&g_xl[base]))[0] = __halves2half2(ll[0], ll[1]);
    ((__half2*)(&g_xl[base]))[1] = __halves2half2(ll[2], ll[3]);
}

// ---------------- kernel 3: fused GEMM (delta + Bp/C) via mma.sync fp16 ----------------
// grid (9, 32): bn<8 -> delta path: BK=64, XOR-swizzled 128B rows, 16 iters.
//               bn==8 -> bc path: BK=32, KST=40 layout, 32 iters.
// CTA tile 128x128, 8 warps each 32(m) x 64(n). cp.async 2-stage pipeline.
#define KST 40                         // bc path smem row stride in fp16 (80B)
#define TILE_B (128 * KST * 2)         // 10240 B per bc tile
#define STAGE_B (4 * TILE_B)           // 40960 B per bc stage
#define TILE2  16384                   // delta tile: 128 rows x 128B
#define STAGE2 (2 * TILE2)             // 32768 B per delta stage
#define SMEM_TOT (2 * STAGE_B)         // 81920 B (covers both layouts)
__global__ __launch_bounds__(256, 2) void k_gemm_mma(const float* __restrict__ bd) {
    extern __shared__ __align__(16) char smem[];
    const uint32_t su = smem_u32(smem);

    int tid = threadIdx.x, wid = tid >> 5, lane = tid & 31;
    int bm = blockIdx.y, bn = blockIdx.x;
    const int m0 = bm * 128, n0 = bn * 128;
    int wm = wid & 3, wn = wid >> 2;

    float acc[2][8][4];
    #pragma unroll
    for (int a = 0; a < 2; a++)
        #pragma unroll
        for (int b = 0; b < 8; b++)
            #pragma unroll
            for (int c = 0; c < 4; c++) acc[a][b][c] = 0.f;

    if (bn < 8) {
        // ================= delta path: BK=64, swizzled =================
        const __half* pA = g_xh + (size_t)m0 * D;
        const __half* pB = g_wth + (size_t)n0 * D;
        auto issue = [&](int k0, int stage) {
            uint32_t sb = su + (uint32_t)(stage * STAGE2);
            #pragma unroll
            for (int j = 0; j < 8; j++) {
                int id = tid + j * 256;
                const int tile = j >> 2;               // 0..1 (compile-time per j)
                int sub = id & 1023;
                int row = sub >> 3, kc = sub & 7;
                const __half* src = (tile == 0 ? pA : pB) + (size_t)row * D + k0 + kc * 8;
                uint32_t dst = sb + (uint32_t)(tile * TILE2 + row * 128 +
                                               ((kc ^ (row & 7)) << 4));
                cp16(dst, src);
            }
            asm volatile("cp.async.commit_group;" ::: "memory");
        };

        int arow = wm * 32 + (lane & 15);
        int brow = wn * 64 + (lane & 7) + ((lane >> 4) << 3);
        uint32_t abase = (uint32_t)(arow * 128);
        uint32_t bbase = (uint32_t)(TILE2 + brow * 128);
        uint32_t rl = (uint32_t)(lane & 7);
        uint32_t ahalf = (uint32_t)(lane >> 4);
        uint32_t bhalf = (uint32_t)((lane >> 3) & 1);

        issue(0, 0);
        for (int i = 0; i < 16; i++) {
            if (i > 0) __syncthreads();
            if (i + 1 < 16) issue((i + 1) * 64, (i + 1) & 1);
            if (i == 15) asm volatile("cp.async.wait_group 0;" ::: "memory");
            else         asm volatile("cp.async.wait_group 1;" ::: "memory");
            __syncthreads();

            uint32_t sb = su + (uint32_t)((i & 1) * STAGE2);
            #pragma unroll
            for (int kk = 0; kk < 4; kk++) {
                uint32_t xa = (((uint32_t)(2 * kk) + ahalf) ^ rl) << 4;
                uint32_t xb = (((uint32_t)(2 * kk) + bhalf) ^ rl) << 4;
                uint32_t ah0[4], ah1[4];
                ldsm4(ah0[0], ah0[1], ah0[2], ah0[3], sb + abase + xa);
                ldsm4(ah1[0], ah1[1], ah1[2], ah1[3], sb + abase + 2048 + xa);
                #pragma unroll
                for (int nb = 0; nb < 4; nb++) {
                    uint32_t bh[4];
                    ldsm4(bh[0], bh[1], bh[2], bh[3],
                          sb + bbase + (uint32_t)(nb * 2048) + xb);
                    mma16816(acc[0][2 * nb],     ah0, bh[0], bh[1]);
                    mma16816(acc[1][2 * nb],     ah1, bh[0], bh[1]);
                    mma16816(acc[0][2 * nb + 1], ah0, bh[2], bh[3]);
                    mma16816(acc[1][2 * nb + 1], ah1, bh[2], bh[3]);
                }
            }
        }

        // epilogue: z -> delta -> (delta, sqrt(delta)*xn)
        const float CTR = 5.00005f, HLF = 4.99995f, INVH = 1.0f / 4.99995f;
        #pragma unroll
        for (int ma = 0; ma < 2; ma++) {
            int row0 = m0 + wm * 32 + ma * 16 + (lane >> 2);
            #pragma unroll
            for (int na = 0; na < 8; na++) {
                int col = n0 + wn * 64 + na * 8 + 2 * (lane & 3);
                float2 bdv = *(const float2*)(bd + col);
                #pragma unroll
                for (int hrow = 0; hrow < 2; hrow++) {
                    int m = row0 + hrow * 8;
                    float z0 = acc[ma][na][2 * hrow]     + bdv.x;
                    float z1 = acc[ma][na][2 * hrow + 1] + bdv.y;
                    float2 xv = *(const float2*)(&g_xn[(size_t)m * D + col]);
                    float sp0 = fmaxf(z0, 0.0f) + log1pf(expf(-fabsf(z0)));
                    float sp1 = fmaxf(z1, 0.0f) + log1pf(expf(-fabsf(z1)));
                    float dl0 = CTR + HLF * tanhf((sp0 - CTR) * INVH);
                    float dl1 = CTR + HLF * tanhf((sp1 - CTR) * INVH);
                    float sx0 = sqrtf(dl0) * xv.x;
                    float sx1 = sqrtf(dl1) * xv.y;
                    *(float2*)(&g_delta[(size_t)m * D + col]) = make_float2(dl0, dl1);
                    *(float2*)(&g_sdx[(size_t)m * D + col])   = make_float2(sx0, sx1);
                }
            }
        }
    } else {
        // ================= bc path: BK=32, KST=40 =================
        const __half* pA0 = g_xh + (size_t)m0 * D;
        const __half* pA1 = g_xl + (size_t)m0 * D;
        const __half* pB0 = g_wbch;
        const __half* pB1 = g_wbcl;

        uint32_t aoff = (uint32_t)((wm * 32 + (lane & 15)) * (KST * 2) + ((lane >> 4) << 4));
        uint32_t boff = (uint32_t)((wn * 64 + (lane & 7) + ((lane >> 4) << 3)) * (KST * 2) +
                                   (((lane >> 3) & 1) << 4));

        auto issue = [&](int k0, int stage) {
            uint32_t sb = su + (uint32_t)(stage * STAGE_B);
            #pragma unroll
            for (int j = 0; j < 8; j++) {
                const int tile = j >> 1;
                int sub = tid + (j & 1) * 256;
                int row = sub >> 2, seg = sub & 3;
                const __half* src;
                if (tile == 0)      src = pA0 + (size_t)row * D + k0 + seg * 8;
                else if (tile == 1) src = pA1 + (size_t)row * D + k0 + seg * 8;
                else if (tile == 2) src = pB0 + (size_t)row * D + k0 + seg * 8;
                else                src = pB1 + (size_t)row * D + k0 + seg * 8;
                cp16(sb + (uint32_t)(tile * TILE_B + row * (KST * 2) + seg * 16), src);
            }
            asm volatile("cp.async.commit_group;" ::: "memory");
        };

        issue(0, 0);
        for (int i = 0; i < 32; i++) {
            if (i > 0) __syncthreads();
            if (i + 1 < 32) issue((i + 1) * 32, (i + 1) & 1);
            if (i == 31) asm volatile("cp.async.wait_group 0;" ::: "memory");
            else         asm volatile("cp.async.wait_group 1;" ::: "memory");
            __syncthreads();

            uint32_t sb = su + (uint32_t)((i & 1) * STAGE_B);
            uint32_t uAh = sb, uAl = sb + TILE_B, uBh = sb + 2 * TILE_B, uBl = sb + 3 * TILE_B;
            #pragma unroll
            for (int kk = 0; kk < 2; kk++) {
                uint32_t kb = (uint32_t)(kk * 32);
                uint32_t ah0[4], ah1[4];
                ldsm4(ah0[0], ah0[1], ah0[2], ah0[3], uAh + aoff + kb);
                ldsm4(ah1[0], ah1[1], ah1[2], ah1[3], uAh + aoff + kb + 16 * KST * 2);
                #pragma unroll
                for (int nb = 0; nb < 2; nb++) {      // bc: only cols 0..31
                    if (wn == 1) continue;
                    uint32_t bh[4];
                    uint32_t bo = boff + kb + (uint32_t)(nb * 16 * KST * 2);
                    ldsm4(bh[0], bh[1], bh[2], bh[3], uBh + bo);
                    mma16816(acc[0][2 * nb],     ah0, bh[0], bh[1]);
                    mma16816(acc[1][2 * nb],     ah1, bh[0], bh[1]);
                    mma16816(acc[0][2 * nb + 1], ah0, bh[2], bh[3]);
                    mma16816(acc[1][2 * nb + 1], ah1, bh[2], bh[3]);
                    uint32_t al0[4], al1[4], bl[4];
                    ldsm4(al0[0], al0[1], al0[2], al0[3], uAl + aoff + kb);
                    ldsm4(al1[0], al1[1], al1[2], al1[3], uAl + aoff + kb + 16 * KST * 2);
                    ldsm4(bl[0], bl[1], bl[2], bl[3], uBl + bo);
                    mma16816(acc[0][2 * nb],     al0, bh[0], bh[1]);
                    mma16816(acc[1][2 * nb],     al1, bh[0], bh[1]);
                    mma16816(acc[0][2 * nb + 1], al0, bh[2], bh[3]);
                    mma16816(acc[1][2 * nb + 1], al1, bh[2], bh[3]);
                    mma16816(acc[0][2 * nb],     ah0, bl[0], bl[1]);
                    mma16816(acc[1][2 * nb],     ah1, bl[0], bl[1]);
                    mma16816(acc[0][2 * nb + 1], ah0, bl[2], bl[3]);
                    mma16816(acc[1][2 * nb + 1], ah1, bl[2], bl[3]);
                }
            }
        }

        if (wn == 0) {
            #pragma unroll
            for (int ma = 0; ma < 2; ma++) {
                int row0 = m0 + wm * 32 + ma * 16 + (lane >> 2);
                #pragma unroll
                for (int na = 0; na < 4; na++) {
                    int col = na * 8 + 2 * (lane & 3);
                    #pragma unroll
                    for (int hrow = 0; hrow < 2; hrow++) {
                        int m = row0 + hrow * 8;
                        *(float2*)(&g_bpc[(size_t)m * 2 * SN + col]) =
                            make_float2(acc[ma][na][2 * hrow], acc[ma][na][2 * hrow + 1]);
                    }
                }
            }
        }
    }
}

// ---------------- kernel 4: chunk-local scan, smem-staged, n-split S=4 ----------------
// CTA = (chunk c, 64-d block); 256 threads = 64 d x 4 s. Double-buffered cp.async over
// 16-t blocks removes global latency from the scan's critical path.
__global__ __launch_bounds__(256) void k_phase2() {
    __shared__ __align__(16) float sdl[2][TB][64];
    __shared__ __align__(16) float ssx[2][TB][64];
    __shared__ __align__(16) float sbp[2][TB][16];
    int b = blockIdx.x;                 // NC * 16
    int c = b >> 4;
    int db = (b & 15) << 6;
    int tid = threadIdx.x;
    int dl = tid >> 2, s = tid & 3;
    int d = db + dl;
    const u64 ONE2 = pack2(1.f, 1.f), TWO2 = pack2(2.f, 2.f), NONE2 = pack2(-1.f, -1.f);
    u64 cA2[2], h2[2], P2[2];
    {
        ulonglong2 v = *(const ulonglong2*)&g_cA[d * SN + s * 4];
        cA2[0] = v.x; cA2[1] = v.y;
    }
    h2[0] = h2[1] = 0ull;
    P2[0] = P2[1] = ONE2;

    int t0 = c * CT;
    auto issue = [&](int tb, int stage) {
        int tbase = t0 + tb * TB;
        {   // delta + sdx: 256 cp16 each
            int t = tid >> 4, seg = tid & 15;
            size_t g = (size_t)(tbase + t) * D + db + seg * 4;
            cp16(smem_u32(&sdl[stage][t][seg * 4]), &g_delta[g]);
            cp16(smem_u32(&ssx[stage][t][seg * 4]), &g_sdx[g]);
        }
        if (tid < 64) {  // Bp: 16 t x 64B
            int t = tid >> 2, seg = tid & 3;
            cp16(smem_u32(&sbp[stage][t][seg * 4]),
                 &g_bpc[(size_t)(tbase + t) * 2 * SN + seg * 4]);
        }
        asm volatile("cp.async.commit_group;" ::: "memory");
    };

    issue(0, 0);
    for (int tb = 0; tb < NTB; tb++) {
        if (tb + 1 < NTB) issue(tb + 1, (tb + 1) & 1);
        if (tb + 1 < NTB) asm volatile("cp.async.wait_group 1;" ::: "memory");
        else              asm volatile("cp.async.wait_group 0;" ::: "memory");
        __syncthreads();
        int st = tb & 1;
        #pragma unroll
        for (int tt = 0; tt < TB; tt++) {
            float dlv = sdl[st][tt][dl];
            float sdx = ssx[st][tt][dl];
            ulonglong2 vb = *(const ulonglong2*)&sbp[st][tt][s * 4];
            u64 dlv2 = pack2(dlv, dlv), sdx2 = pack2(sdx, sdx);
            u64 bp2[2] = {vb.x, vb.y};
            #pragma unroll
            for (int p = 0; p < 2; p++) {
                u64 den2 = fma2(cA2[p], dlv2, ONE2);       // 1 + 0.5*delta*|A| > 1
                float2 dd = unpack2(den2);
                u64 dinv2 = pack2(frcp(dd.x), frcp(dd.y));
                u64 ab2 = fma2(dinv2, TWO2, NONE2);        // (1+hf)/(1-hf) = 2*dinv - 1
                u64 bx2 = mul2(mul2(bp2[p], dinv2), sdx2);
                h2[p] = fma2(ab2, h2[p], bx2);
                P2[p] = mul2(P2[p], ab2);
            }
        }
        __syncthreads();   // all reads of buffer st done before it is refilled
    }
    size_t basei = (size_t)c * (D * SN) + (size_t)d * SN + s * 4;
    ulonglong2 vp, vs;
    vp.x = P2[0]; vp.y = P2[1];
    vs.x = h2[0]; vs.y = h2[1];
    *(ulonglong2*)&g_P[basei] = vp;
    *(ulonglong2*)&g_S[basei] = vs;
}

// ---------------- kernel 5: scan over chunk summaries ----------------
__global__ __launch_bounds__(256) void k_phase3() {
    int s = blockIdx.x * 256 + threadIdx.x;  // D*SN threads
    float H = 0.f;
    #pragma unroll 4
    for (int c = 0; c < NC; c++) {
        size_t idx = (size_t)c * (D * SN) + s;
        g_hin[idx] = H;
        H = fmaf(g_P[idx], H, g_S[idx]);
    }
}

// ---------------- kernel 6: recompute with true init, emit y (smem-staged) ----------------
__global__ __launch_bounds__(256) void k_phase4(const float* __restrict__ Dskip,
                                                float* __restrict__ y) {
    __shared__ __align__(16) float sdl[2][TB][64];
    __shared__ __align__(16) float ssx[2][TB][64];
    __shared__ __align__(16) float sxn[2][TB][64];
    __shared__ __align__(16) float sbc[2][TB][32];
    int b = blockIdx.x;
    int c = b >> 4;
    int db = (b & 15) << 6;
    int tid = threadIdx.x;
    int dl = tid >> 2, s = tid & 3;
    int d = db + dl;
    const u64 ONE2 = pack2(1.f, 1.f), TWO2 = pack2(2.f, 2.f), NONE2 = pack2(-1.f, -1.f);
    u64 cA2[2], h2[2];
    {
        ulonglong2 v = *(const ulonglong2*)&g_cA[d * SN + s * 4];
        cA2[0] = v.x; cA2[1] = v.y;
    }
    size_t basei = (size_t)c * (D * SN) + (size_t)d * SN + s * 4;
    {
        ulonglong2 v = *(const ulonglong2*)&g_hin[basei];
        h2[0] = v.x; h2[1] = v.y;
    }
    float dsk = Dskip[d];

    int t0 = c * CT;
    auto issue = [&](int tb, int stage) {
        int tbase = t0 + tb * TB;
        {
            int t = tid >> 4, seg = tid & 15;
            size_t g = (size_t)(tbase + t) * D + db + seg * 4;
            cp16(smem_u32(&sdl[stage][t][seg * 4]), &g_delta[g]);
            cp16(smem_u32(&ssx[stage][t][seg * 4]), &g_sdx[g]);
            cp16(smem_u32(&sxn[stage][t][seg * 4]), &g_xn[g]);
        }
        if (tid < 128) {  // Bp+C: 16 t x 128B
            int t = tid >> 3, seg = tid & 7;
            cp16(smem_u32(&sbc[stage][t][seg * 4]),
                 &g_bpc[(size_t)(tbase + t) * 2 * SN + seg * 4]);
        }
        asm volatile("cp.async.commit_group;" ::: "memory");
    };

    issue(0, 0);
    for (int tb = 0; tb < NTB; tb++) {
        if (tb + 1 < NTB) issue(tb + 1, (tb + 1) & 1);
        if (tb + 1 < NTB) asm volatile("cp.async.wait_group 1;" ::: "memory");
        else              asm volatile("cp.async.wait_group 0;" ::: "memory");
        __syncthreads();
        int st = tb & 1;
        #pragma unroll
        for (int tt = 0; tt < TB; tt++) {
            int t = t0 + tb * TB + tt;
            float dlv = sdl[st][tt][dl];
            float sdx = ssx[st][tt][dl];
            float xnv = sxn[st][tt][dl];
            ulonglong2 vb = *(const ulonglong2*)&sbc[st][tt][s * 4];
            ulonglong2 vc = *(const ulonglong2*)&sbc[st][tt][16 + s * 4];
            u64 dlv2 = pack2(dlv, dlv), sdx2 = pack2(sdx, sdx);
            u64 bp2[2] = {vb.x, vb.y};
            u64 cc2[2] = {vc.x, vc.y};
            u64 acca = 0ull, accb = 0ull;
            #pragma unroll
            for (int p = 0; p < 2; p++) {
                u64 den2 = fma2(cA2[p], dlv2, ONE2);
                float2 dd = unpack2(den2);
                u64 dinv2 = pack2(frcp(dd.x), frcp(dd.y));
                u64 ab2 = fma2(dinv2, TWO2, NONE2);
                u64 bx2 = mul2(mul2(bp2[p], dinv2), sdx2);
                h2[p] = fma2(ab2, h2[p], bx2);
                if (p) accb = fma2(cc2[p], h2[p], accb);
                else   acca = fma2(cc2[p], h2[p], acca);
            }
            float2 sv = unpack2(add2(acca, accb));
            float acc = sv.x + sv.y;
            // reduce across the 4-lane n-split group
            acc += __shfl_xor_sync(0xFFFFFFFFu, acc, 1);
            acc += __shfl_xor_sync(0xFFFFFFFFu, acc, 2);
            if (s == 0) y[(size_t)t * D + d] = fmaf(dsk, xnv, acc);
        }
        __syncthreads();
    }
}

// ---------------- launch ----------------
extern "C" void kernel_launch(void* const* d_in, const int* in_sizes, int n_in,
                              void* d_out, int out_size) {
    const float* x       = (const float*)d_in[0];
    const float* A_log   = (const float*)d_in[1];
    const float* W_delta = (const float*)d_in[2];
    const float* b_delta = (const float*)d_in[3];
    const float* W_B     = (const float*)d_in[4];
    const float* W_C     = (const float*)d_in[5];
    const float* D_skip  = (const float*)d_in[6];
    const float* norm_w  = (const float*)d_in[7];
    float* y = (float*)d_out;

    cudaFuncSetAttribute(k_gemm_mma, cudaFuncAttributeMaxDynamicSharedMemorySize,
                         SMEM_TOT);

    k_wt<<<dim3(32, 32), dim3(32, 8)>>>(W_delta);
    k_wbc<<<128 * D / 256, 256>>>(W_B, W_C, A_log);
    k_rms<<<L, 256>>>(x, norm_w);
    k_gemm_mma<<<dim3(9, 32), 256, SMEM_TOT>>>(b_delta);
    k_phase2<<<NC * 16, 256>>>();
    k_phase3<<<D * SN / 256, 256>>>();
    k_phase4<<<NC * 16, 256>>>(D_skip, y);
}

// round 17
// speedup vs baseline: 1.8307x; 1.0330x over previous
#include <cuda_runtime.h>
#include <cuda_fp16.h>
#include <math.h>
#include <stdint.h>

// Problem shape (fixed by dataset)
#define L   4096
#define D   1024
#define SN  16
#define NC  64      // number of chunks
#define CT  64      // chunk length; NC*CT == L
#define TB  16      // t-block for phase smem staging
#define NTB (CT / TB)

typedef unsigned long long u64;

// ---------------- scratch (static device globals; no allocation) ----------------
__device__ float g_xn[L * D];                  // normalized input (fp32)
__device__ __half g_xh[L * D];                 // fp16 hi of xn
__device__ __half g_xl[L * D];                 // fp16 lo of xn (bc tile only)
__device__ __half g_wth[D * D];                // W_delta^T fp16 [n][k]
__device__ __half g_wbch[128 * D];             // [WB|WC|0]^T hi [n][k], n<32 real
__device__ __half g_wbcl[128 * D];             // [WB|WC|0]^T lo
__device__ __half2 g_dsx[L * D];               // packed (delta, sqrt(delta)*xn) fp16
__device__ float g_bpc[L * 2 * SN];            // per-t: Bp[0..15], C[16..31]
__device__ float g_cA[D * SN];                 // +0.5*exp(A_log)   (positive!)
__device__ float g_P[NC * D * SN];             // per-chunk product of A_bar
__device__ float g_S[NC * D * SN];             // per-chunk end-state from h0=0
__device__ float g_hin[NC * D * SN];           // per-chunk initial state

// ---------------- helpers ----------------
__device__ __forceinline__ float frcp(float x) {
    float r;
    asm("rcp.approx.f32 %0, %1;" : "=f"(r) : "f"(x));
    return r;
}
__device__ __forceinline__ uint32_t smem_u32(const void* p) {
    uint32_t a;
    asm("{ .reg .u64 t; cvta.to.shared.u64 t, %1; cvt.u32.u64 %0, t; }" : "=r"(a) : "l"(p));
    return a;
}
__device__ __forceinline__ void ldsm4(uint32_t& r0, uint32_t& r1, uint32_t& r2, uint32_t& r3,
                                      uint32_t addr) {
    asm volatile("ldmatrix.sync.aligned.m8n8.x4.shared.b16 {%0,%1,%2,%3}, [%4];"
                 : "=r"(r0), "=r"(r1), "=r"(r2), "=r"(r3) : "r"(addr));
}
__device__ __forceinline__ void mma16816(float* d, const uint32_t* a, uint32_t b0, uint32_t b1) {
    asm volatile(
        "mma.sync.aligned.m16n8k16.row.col.f32.f16.f16.f32 "
        "{%0,%1,%2,%3}, {%4,%5,%6,%7}, {%8,%9}, {%0,%1,%2,%3};"
        : "+f"(d[0]), "+f"(d[1]), "+f"(d[2]), "+f"(d[3])
        : "r"(a[0]), "r"(a[1]), "r"(a[2]), "r"(a[3]), "r"(b0), "r"(b1));
}
__device__ __forceinline__ void cp16(uint32_t dst, const void* src) {
    asm volatile("cp.async.cg.shared.global [%0], [%1], 16;" :: "r"(dst), "l"(src) : "memory");
}
__device__ __forceinline__ u64 pack2(float lo, float hi) {
    u64 r;
    asm("mov.b64 %0, {%1,%2};" : "=l"(r) : "f"(lo), "f"(hi));
    return r;
}
__device__ __forceinline__ float2 unpack2(u64 v) {
    float lo, hi;
    asm("mov.b64 {%0,%1}, %2;" : "=f"(lo), "=f"(hi) : "l"(v));
    return make_float2(lo, hi);
}
__device__ __forceinline__ u64 fma2(u64 a, u64 b, u64 c) {
    u64 d;
    asm("fma.rn.f32x2 %0, %1, %2, %3;" : "=l"(d) : "l"(a), "l"(b), "l"(c));
    return d;
}
__device__ __forceinline__ u64 mul2(u64 a, u64 b) {
    u64 d;
    asm("mul.rn.f32x2 %0, %1, %2;" : "=l"(d) : "l"(a), "l"(b));
    return d;
}
__device__ __forceinline__ u64 add2(u64 a, u64 b) {
    u64 d;
    asm("add.rn.f32x2 %0, %1, %2;" : "=l"(d) : "l"(a), "l"(b));
    return d;
}
__device__ __forceinline__ uint32_t h2_bits(__half2 h) {
    return *reinterpret_cast<uint32_t*>(&h);
}

// ---------------- kernel 0: merged prep (W_delta transpose + [WB|WC] pack + cA) --------
__global__ __launch_bounds__(256) void k_prep(const float* __restrict__ W,
                                              const float* __restrict__ WB,
                                              const float* __restrict__ WC,
                                              const float* __restrict__ A_log) {
    int bid = blockIdx.x;
    int tid = threadIdx.x;
    if (bid < 1024) {
        // W_delta^T -> fp16
        __shared__ float tile[32][33];
        int bx = bid & 31, by = bid >> 5;
        int tx = tid & 31, ty = tid >> 5;   // 32 x 8
        #pragma unroll
        for (int i = 0; i < 32; i += 8)
            tile[ty + i][tx] = W[(size_t)(by * 32 + ty + i) * D + bx * 32 + tx];
        __syncthreads();
        #pragma unroll
        for (int i = 0; i < 32; i += 8) {
            int n = bx * 32 + ty + i;
            int k = by * 32 + tx;
            g_wth[(size_t)n * D + k] = __float2half(tile[tx][ty + i]);  // = W[k][n]
        }
    } else {
        int idx = (bid - 1024) * 256 + tid;   // 128*1024
        if (idx < D * SN) g_cA[idx] = 0.5f * expf(A_log[idx]);
        int n = idx >> 10, k = idx & 1023;
        float v = 0.f;
        if (n < SN) v = WB[(size_t)k * SN + n];
        else if (n < 2 * SN) v = WC[(size_t)k * SN + n - SN];
        __half h = __float2half(v);
        __half l = __float2half(v - __half2float(h));
        g_wbch[idx] = h;
        g_wbcl[idx] = l;
    }
}

// ---------------- kernel 1: RMSNorm (+ fp16 hi/lo split of xn) ----------------
__global__ __launch_bounds__(256) void k_rms(const float* __restrict__ x,
                                             const float* __restrict__ w) {
    int row = blockIdx.x;
    int tid = threadIdx.x;
    const float4 xv = *(const float4*)(x + (size_t)row * D + tid * 4);
    float s = xv.x * xv.x + xv.y * xv.y + xv.z * xv.z + xv.w * xv.w;
    #pragma unroll
    for (int o = 16; o > 0; o >>= 1) s += __shfl_xor_sync(0xFFFFFFFFu, s, o);
    __shared__ float red[8];
    int warp = tid >> 5, lane = tid & 31;
    if (lane == 0) red[warp] = s;
    __syncthreads();
    float tot = 0.f;
    #pragma unroll
    for (int i = 0; i < 8; i++) tot += red[i];
    float inv = 1.0f / sqrtf(tot * (1.0f / (float)D) + 1e-6f);
    const float4 wv = *(const float4*)(w + tid * 4);
    float4 o;
    o.x = wv.x * xv.x * inv;
    o.y = wv.y * xv.y * inv;
    o.z = wv.z * xv.z * inv;
    o.w = wv.w * xv.w * inv;
    size_t base = (size_t)row * D + tid * 4;
    *(float4*)(&g_xn[base]) = o;
    float vv[4] = {o.x, o.y, o.z, o.w};
    __half hh[4], ll[4];
    #pragma unroll
    for (int i = 0; i < 4; i++) {
        hh[i] = __float2half(vv[i]);
        ll[i] = __float2half(vv[i] - __half2float(hh[i]));
    }
    ((__half2*)(&g_xh[base]))[0] = __halves2half2(hh[0], hh[1]);
    ((__half2*)(&g_xh[base]))[1] = __halves2half2(hh[2], hh[3]);
    ((__half2*)(&g_xl[base]))[0] = __halves2half2(ll[0], ll[1]);
    ((__half2*)(&g_xl[base]))[1] = __halves2half2(ll[2], ll[3]);
}

// ---------------- kernel 3: fused GEMM (delta + Bp/C) via mma.sync fp16 ----------------
// grid (9, 32): bn<8 -> delta path: BK=64, XOR-swizzled 128B rows, 16 iters.
//               bn==8 -> bc path: BK=32, KST=40 layout, 32 iters.
// CTA tile 128x128, 8 warps each 32(m) x 64(n). cp.async 2-stage pipeline.
#define KST 40                         // bc path smem row stride in fp16 (80B)
#define TILE_B (128 * KST * 2)         // 10240 B per bc tile
#define STAGE_B (4 * TILE_B)           // 40960 B per bc stage
#define TILE2  16384                   // delta tile: 128 rows x 128B
#define STAGE2 (2 * TILE2)             // 32768 B per delta stage
#define SMEM_TOT (2 * STAGE_B)         // 81920 B (covers both layouts)
__global__ __launch_bounds__(256, 2) void k_gemm_mma(const float* __restrict__ bd) {
    extern __shared__ __align__(16) char smem[];
    const uint32_t su = smem_u32(smem);

    int tid = threadIdx.x, wid = tid >> 5, lane = tid & 31;
    int bm = blockIdx.y, bn = blockIdx.x;
    const int m0 = bm * 128, n0 = bn * 128;
    int wm = wid & 3, wn = wid >> 2;

    float acc[2][8][4];
    #pragma unroll
    for (int a = 0; a < 2; a++)
        #pragma unroll
        for (int b = 0; b < 8; b++)
            #pragma unroll
            for (int c = 0; c < 4; c++) acc[a][b][c] = 0.f;

    if (bn < 8) {
        // ================= delta path: BK=64, swizzled =================
        const __half* pA = g_xh + (size_t)m0 * D;
        const __half* pB = g_wth + (size_t)n0 * D;
        auto issue = [&](int k0, int stage) {
            uint32_t sb = su + (uint32_t)(stage * STAGE2);
            #pragma unroll
            for (int j = 0; j < 8; j++) {
                int id = tid + j * 256;
                const int tile = j >> 2;               // 0..1 (compile-time per j)
                int sub = id & 1023;
                int row = sub >> 3, kc = sub & 7;
                const __half* src = (tile == 0 ? pA : pB) + (size_t)row * D + k0 + kc * 8;
                uint32_t dst = sb + (uint32_t)(tile * TILE2 + row * 128 +
                                               ((kc ^ (row & 7)) << 4));
                cp16(dst, src);
            }
            asm volatile("cp.async.commit_group;" ::: "memory");
        };

        int arow = wm * 32 + (lane & 15);
        int brow = wn * 64 + (lane & 7) + ((lane >> 4) << 3);
        uint32_t abase = (uint32_t)(arow * 128);
        uint32_t bbase = (uint32_t)(TILE2 + brow * 128);
        uint32_t rl = (uint32_t)(lane & 7);
        uint32_t ahalf = (uint32_t)(lane >> 4);
        uint32_t bhalf = (uint32_t)((lane >> 3) & 1);

        issue(0, 0);
        for (int i = 0; i < 16; i++) {
            if (i > 0) __syncthreads();
            if (i + 1 < 16) issue((i + 1) * 64, (i + 1) & 1);
            if (i == 15) asm volatile("cp.async.wait_group 0;" ::: "memory");
            else         asm volatile("cp.async.wait_group 1;" ::: "memory");
            __syncthreads();

            uint32_t sb = su + (uint32_t)((i & 1) * STAGE2);
            #pragma unroll
            for (int kk = 0; kk < 4; kk++) {
                uint32_t xa = (((uint32_t)(2 * kk) + ahalf) ^ rl) << 4;
                uint32_t xb = (((uint32_t)(2 * kk) + bhalf) ^ rl) << 4;
                uint32_t ah0[4], ah1[4];
                ldsm4(ah0[0], ah0[1], ah0[2], ah0[3], sb + abase + xa);
                ldsm4(ah1[0], ah1[1], ah1[2], ah1[3], sb + abase + 2048 + xa);
                #pragma unroll
                for (int nb = 0; nb < 4; nb++) {
                    uint32_t bh[4];
                    ldsm4(bh[0], bh[1], bh[2], bh[3],
                          sb + bbase + (uint32_t)(nb * 2048) + xb);
                    mma16816(acc[0][2 * nb],     ah0, bh[0], bh[1]);
                    mma16816(acc[1][2 * nb],     ah1, bh[0], bh[1]);
                    mma16816(acc[0][2 * nb + 1], ah0, bh[2], bh[3]);
                    mma16816(acc[1][2 * nb + 1], ah1, bh[2], bh[3]);
                }
            }
        }

        // epilogue: z -> delta -> packed (delta, sqrt(delta)*xn) fp16
        const float CTR = 5.00005f, HLF = 4.99995f, INVH = 1.0f / 4.99995f;
        #pragma unroll
        for (int ma = 0; ma < 2; ma++) {
            int row0 = m0 + wm * 32 + ma * 16 + (lane >> 2);
            #pragma unroll
            for (int na = 0; na < 8; na++) {
                int col = n0 + wn * 64 + na * 8 + 2 * (lane & 3);
                float2 bdv = *(const float2*)(bd + col);
                #pragma unroll
                for (int hrow = 0; hrow < 2; hrow++) {
                    int m = row0 + hrow * 8;
                    float z0 = acc[ma][na][2 * hrow]     + bdv.x;
                    float z1 = acc[ma][na][2 * hrow + 1] + bdv.y;
                    float2 xv = *(const float2*)(&g_xn[(size_t)m * D + col]);
                    float sp0 = fmaxf(z0, 0.0f) + log1pf(expf(-fabsf(z0)));
                    float sp1 = fmaxf(z1, 0.0f) + log1pf(expf(-fabsf(z1)));
                    float dl0 = CTR + HLF * tanhf((sp0 - CTR) * INVH);
                    float dl1 = CTR + HLF * tanhf((sp1 - CTR) * INVH);
                    float sx0 = sqrtf(dl0) * xv.x;
                    float sx1 = sqrtf(dl1) * xv.y;
                    uint2 pk;
                    pk.x = h2_bits(__floats2half2_rn(dl0, sx0));
                    pk.y = h2_bits(__floats2half2_rn(dl1, sx1));
                    *(uint2*)(&g_dsx[(size_t)m * D + col]) = pk;
                }
            }
        }
    } else {
        // ================= bc path: BK=32, KST=40 =================
        const __half* pA0 = g_xh + (size_t)m0 * D;
        const __half* pA1 = g_xl + (size_t)m0 * D;
        const __half* pB0 = g_wbch;
        const __half* pB1 = g_wbcl;

        uint32_t aoff = (uint32_t)((wm * 32 + (lane & 15)) * (KST * 2) + ((lane >> 4) << 4));
        uint32_t boff = (uint32_t)((wn * 64 + (lane & 7) + ((lane >> 4) << 3)) * (KST * 2) +
                                   (((lane >> 3) & 1) << 4));

        auto issue = [&](int k0, int stage) {
            uint32_t sb = su + (uint32_t)(stage * STAGE_B);
            #pragma unroll
            for (int j = 0; j < 8; j++) {
                const int tile = j >> 1;
                int sub = tid + (j & 1) * 256;
                int row = sub >> 2, seg = sub & 3;
                const __half* src;
                if (tile == 0)      src = pA0 + (size_t)row * D + k0 + seg * 8;
                else if (tile == 1) src = pA1 + (size_t)row * D + k0 + seg * 8;
                else if (tile == 2) src = pB0 + (size_t)row * D + k0 + seg * 8;
                else                src = pB1 + (size_t)row * D + k0 + seg * 8;
                cp16(sb + (uint32_t)(tile * TILE_B + row * (KST * 2) + seg * 16), src);
            }
            asm volatile("cp.async.commit_group;" ::: "memory");
        };

        issue(0, 0);
        for (int i = 0; i < 32; i++) {
            if (i > 0) __syncthreads();
            if (i + 1 < 32) issue((i + 1) * 32, (i + 1) & 1);
            if (i == 31) asm volatile("cp.async.wait_group 0;" ::: "memory");
            else         asm volatile("cp.async.wait_group 1;" ::: "memory");
            __syncthreads();

            uint32_t sb = su + (uint32_t)((i & 1) * STAGE_B);
            uint32_t uAh = sb, uAl = sb + TILE_B, uBh = sb + 2 * TILE_B, uBl = sb + 3 * TILE_B;
            #pragma unroll
            for (int kk = 0; kk < 2; kk++) {
                uint32_t kb = (uint32_t)(kk * 32);
                uint32_t ah0[4], ah1[4];
                ldsm4(ah0[0], ah0[1], ah0[2], ah0[3], uAh + aoff + kb);
                ldsm4(ah1[0], ah1[1], ah1[2], ah1[3], uAh + aoff + kb + 16 * KST * 2);
                #pragma unroll
                for (int nb = 0; nb < 2; nb++) {      // bc: only cols 0..31
                    if (wn == 1) continue;
                    uint32_t bh[4];
                    uint32_t bo = boff + kb + (uint32_t)(nb * 16 * KST * 2);
                    ldsm4(bh[0], bh[1], bh[2], bh[3], uBh + bo);
                    mma16816(acc[0][2 * nb],     ah0, bh[0], bh[1]);
                    mma16816(acc[1][2 * nb],     ah1, bh[0], bh[1]);
                    mma16816(acc[0][2 * nb + 1], ah0, bh[2], bh[3]);
                    mma16816(acc[1][2 * nb + 1], ah1, bh[2], bh[3]);
                    uint32_t al0[4], al1[4], bl[4];
                    ldsm4(al0[0], al0[1], al0[2], al0[3], uAl + aoff + kb);
                    ldsm4(al1[0], al1[1], al1[2], al1[3], uAl + aoff + kb + 16 * KST * 2);
                    ldsm4(bl[0], bl[1], bl[2], bl[3], uBl + bo);
                    mma16816(acc[0][2 * nb],     al0, bh[0], bh[1]);
                    mma16816(acc[1][2 * nb],     al1, bh[0], bh[1]);
                    mma16816(acc[0][2 * nb + 1], al0, bh[2], bh[3]);
                    mma16816(acc[1][2 * nb + 1], al1, bh[2], bh[3]);
                    mma16816(acc[0][2 * nb],     ah0, bl[0], bl[1]);
                    mma16816(acc[1][2 * nb],     ah1, bl[0], bl[1]);
                    mma16816(acc[0][2 * nb + 1], ah0, bl[2], bl[3]);
                    mma16816(acc[1][2 * nb + 1], ah1, bl[2], bl[3]);
                }
            }
        }

        if (wn == 0) {
            #pragma unroll
            for (int ma = 0; ma < 2; ma++) {
                int row0 = m0 + wm * 32 + ma * 16 + (lane >> 2);
                #pragma unroll
                for (int na = 0; na < 4; na++) {
                    int col = na * 8 + 2 * (lane & 3);
                    #pragma unroll
                    for (int hrow = 0; hrow < 2; hrow++) {
                        int m = row0 + hrow * 8;
                        *(float2*)(&g_bpc[(size_t)m * 2 * SN + col]) =
                            make_float2(acc[ma][na][2 * hrow], acc[ma][na][2 * hrow + 1]);
                    }
                }
            }
        }
    }
}

// ---------------- kernel 4: chunk-local scan, smem-staged, n-split S=4 ----------------
// CTA = (chunk c, 64-d block); 256 threads = 64 d x 4 s. Double-buffered cp.async over
// 16-t blocks; (delta,sdx) packed fp16 halves the stream.
__global__ __launch_bounds__(256) void k_phase2() {
    __shared__ __align__(16) __half2 sds[2][TB][64];
    __shared__ __align__(16) float sbp[2][TB][16];
    int b = blockIdx.x;                 // NC * 16
    int c = b >> 4;
    int db = (b & 15) << 6;
    int tid = threadIdx.x;
    int dl = tid >> 2, s = tid & 3;
    int d = db + dl;
    const u64 ONE2 = pack2(1.f, 1.f), TWO2 = pack2(2.f, 2.f), NONE2 = pack2(-1.f, -1.f);
    u64 cA2[2], h2[2], P2[2];
    {
        ulonglong2 v = *(const ulonglong2*)&g_cA[d * SN + s * 4];
        cA2[0] = v.x; cA2[1] = v.y;
    }
    h2[0] = h2[1] = 0ull;
    P2[0] = P2[1] = ONE2;

    int t0 = c * CT;
    auto issue = [&](int tb, int stage) {
        int tbase = t0 + tb * TB;
        {   // (delta,sdx) half2: 16 segs of 16B per t
            int t = tid >> 4, seg = tid & 15;
            cp16(smem_u32(&sds[stage][t][seg * 4]),
                 &g_dsx[(size_t)(tbase + t) * D + db + seg * 4]);
        }
        if (tid < 64) {  // Bp: 16 t x 64B
            int t = tid >> 2, seg = tid & 3;
            cp16(smem_u32(&sbp[stage][t][seg * 4]),
                 &g_bpc[(size_t)(tbase + t) * 2 * SN + seg * 4]);
        }
        asm volatile("cp.async.commit_group;" ::: "memory");
    };

    issue(0, 0);
    for (int tb = 0; tb < NTB; tb++) {
        if (tb + 1 < NTB) issue(tb + 1, (tb + 1) & 1);
        if (tb + 1 < NTB) asm volatile("cp.async.wait_group 1;" ::: "memory");
        else              asm volatile("cp.async.wait_group 0;" ::: "memory");
        __syncthreads();
        int st = tb & 1;
        #pragma unroll
        for (int tt = 0; tt < TB; tt++) {
            float2 ds = __half22float2(sds[st][tt][dl]);
            float dlv = ds.x, sdx = ds.y;
            ulonglong2 vb = *(const ulonglong2*)&sbp[st][tt][s * 4];
            u64 dlv2 = pack2(dlv, dlv), sdx2 = pack2(sdx, sdx);
            u64 bp2[2] = {vb.x, vb.y};
            #pragma unroll
            for (int p = 0; p < 2; p++) {
                u64 den2 = fma2(cA2[p], dlv2, ONE2);       // 1 + 0.5*delta*|A| > 1
                float2 dd = unpack2(den2);
                u64 dinv2 = pack2(frcp(dd.x), frcp(dd.y));
                u64 ab2 = fma2(dinv2, TWO2, NONE2);        // (1+hf)/(1-hf) = 2*dinv - 1
                u64 bx2 = mul2(mul2(bp2[p], dinv2), sdx2);
                h2[p] = fma2(ab2, h2[p], bx2);
                P2[p] = mul2(P2[p], ab2);
            }
        }
        __syncthreads();   // all reads of buffer st done before it is refilled
    }
    size_t basei = (size_t)c * (D * SN) + (size_t)d * SN + s * 4;
    ulonglong2 vp, vs;
    vp.x = P2[0]; vp.y = P2[1];
    vs.x = h2[0]; vs.y = h2[1];
    *(ulonglong2*)&g_P[basei] = vp;
    *(ulonglong2*)&g_S[basei] = vs;
}

// ---------------- kernel 5: scan over chunk summaries ----------------
__global__ __launch_bounds__(256) void k_phase3() {
    int s = blockIdx.x * 256 + threadIdx.x;  // D*SN threads
    float H = 0.f;
    #pragma unroll 4
    for (int c = 0; c < NC; c++) {
        size_t idx = (size_t)c * (D * SN) + s;
        g_hin[idx] = H;
        H = fmaf(g_P[idx], H, g_S[idx]);
    }
}

// ---------------- kernel 6: recompute with true init, emit y (smem-staged) ----------------
__global__ __launch_bounds__(256) void k_phase4(const float* __restrict__ Dskip,
                                                float* __restrict__ y) {
    __shared__ __align__(16) __half2 sds[2][TB][64];
    __shared__ __align__(16) __half sxh[2][TB][64];
    __shared__ __align__(16) float sbc[2][TB][32];
    int b = blockIdx.x;
    int c = b >> 4;
    int db = (b & 15) << 6;
    int tid = threadIdx.x;
    int dl = tid >> 2, s = tid & 3;
    int d = db + dl;
    const u64 ONE2 = pack2(1.f, 1.f), TWO2 = pack2(2.f, 2.f), NONE2 = pack2(-1.f, -1.f);
    u64 cA2[2], h2[2];
    {
        ulonglong2 v = *(const ulonglong2*)&g_cA[d * SN + s * 4];
        cA2[0] = v.x; cA2[1] = v.y;
    }
    size_t basei = (size_t)c * (D * SN) + (size_t)d * SN + s * 4;
    {
        ulonglong2 v = *(const ulonglong2*)&g_hin[basei];
        h2[0] = v.x; h2[1] = v.y;
    }
    float dsk = Dskip[d];

    int t0 = c * CT;
    auto issue = [&](int tb, int stage) {
        int tbase = t0 + tb * TB;
        {   // (delta,sdx) half2
            int t = tid >> 4, seg = tid & 15;
            cp16(smem_u32(&sds[stage][t][seg * 4]),
                 &g_dsx[(size_t)(tbase + t) * D + db + seg * 4]);
        }
        if (tid < 128) {  // xn fp16: 16 t x 128B (8 segs of 16B per t)
            int t = tid >> 3, seg = tid & 7;
            cp16(smem_u32(&sxh[stage][t][seg * 8]),
                 &g_xh[(size_t)(tbase + t) * D + db + seg * 8]);
        } else {          // Bp+C: 16 t x 128B
            int t2 = (tid - 128) >> 3, seg = (tid - 128) & 7;
            cp16(smem_u32(&sbc[stage][t2][seg * 4]),
                 &g_bpc[(size_t)(tbase + t2) * 2 * SN + seg * 4]);
        }
        asm volatile("cp.async.commit_group;" ::: "memory");
    };

    issue(0, 0);
    for (int tb = 0; tb < NTB; tb++) {
        if (tb + 1 < NTB) issue(tb + 1, (tb + 1) & 1);
        if (tb + 1 < NTB) asm volatile("cp.async.wait_group 1;" ::: "memory");
        else              asm volatile("cp.async.wait_group 0;" ::: "memory");
        __syncthreads();
        int st = tb & 1;
        #pragma unroll
        for (int tt = 0; tt < TB; tt++) {
            int t = t0 + tb * TB + tt;
            float2 ds = __half22float2(sds[st][tt][dl]);
            float dlv = ds.x, sdx = ds.y;
            float xnv = __half2float(sxh[st][tt][dl]);
            ulonglong2 vb = *(const ulonglong2*)&sbc[st][tt][s * 4];
            ulonglong2 vc = *(const ulonglong2*)&sbc[st][tt][16 + s * 4];
            u64 dlv2 = pack2(dlv, dlv), sdx2 = pack2(sdx, sdx);
            u64 bp2[2] = {vb.x, vb.y};
            u64 cc2[2] = {vc.x, vc.y};
            u64 acca = 0ull, accb = 0ull;
            #pragma unroll
            for (int p = 0; p < 2; p++) {
                u64 den2 = fma2(cA2[p], dlv2, ONE2);
                float2 dd = unpack2(den2);
                u64 dinv2 = pack2(frcp(dd.x), frcp(dd.y));
                u64 ab2 = fma2(dinv2, TWO2, NONE2);
                u64 bx2 = mul2(mul2(bp2[p], dinv2), sdx2);
                h2[p] = fma2(ab2, h2[p], bx2);
                if (p) accb = fma2(cc2[p], h2[p], accb);
                else   acca = fma2(cc2[p], h2[p], acca);
            }
            float2 sv = unpack2(add2(acca, accb));
            float acc = sv.x + sv.y;
            // reduce across the 4-lane n-split group
            acc += __shfl_xor_sync(0xFFFFFFFFu, acc, 1);
            acc += __shfl_xor_sync(0xFFFFFFFFu, acc, 2);
            if (s == 0) y[(size_t)t * D + d] = fmaf(dsk, xnv, acc);
        }
        __syncthreads();
    }
}

// ---------------- launch ----------------
extern "C" void kernel_launch(void* const* d_in, const int* in_sizes, int n_in,
                              void* d_out, int out_size) {
    const float* x       = (const float*)d_in[0];
    const float* A_log   = (const float*)d_in[1];
    const float* W_delta = (const float*)d_in[2];
    const float* b_delta = (const float*)d_in[3];
    const float* W_B     = (const float*)d_in[4];
    const float* W_C     = (const float*)d_in[5];
    const float* D_skip  = (const float*)d_in[6];
    const float* norm_w  = (const float*)d_in[7];
    float* y = (float*)d_out;

    cudaFuncSetAttribute(k_gemm_mma, cudaFuncAttributeMaxDynamicSharedMemorySize,
                         SMEM_TOT);

    k_prep<<<1536, 256>>>(W_delta, W_B, W_C, A_log);
    k_rms<<<L, 256>>>(x, norm_w);
    k_gemm_mma<<<dim3(9, 32), 256, SMEM_TOT>>>(b_delta);
    k_phase2<<<NC * 16, 256>>>();
    k_phase3<<<D * SN / 256, 256>>>();
    k_phase4<<<NC * 16, 256>>>(D_skip, y);
}